// round 5
// baseline (speedup 1.0000x reference)
#include <cuda_runtime.h>

#define NUM_FACES 13776
#define MAXC 8
#define EPSF 1e-8f
#define GRID 148
#define TPB 1024

// ---- device scratch (static; no runtime allocations) ----
__device__ float4 g_bbmin[NUM_FACES];     // (minx,miny,minz, face_id0 bits)
__device__ float4 g_bbmax[NUM_FACES];     // (maxx,maxy,maxz, face_id1 bits)
__device__ int    g_f2[NUM_FACES];        // face_id2
__device__ float  g_tri[NUM_FACES * 12];  // 9 floats per face, padded to 48B
__device__ int    g_cnt[NUM_FACES];       // collisions found per row (<= 8)
__device__ int    g_pairs[NUM_FACES * MAXC];
__device__ double g_accum;
__device__ unsigned g_bar_count;
__device__ volatile unsigned g_bar_sense;
__device__ unsigned g_done;

// Sense-reversing grid barrier. Safe: 148 blocks x 1024 thr at 1 block/SM ->
// wave-1 placement keeps every block resident while spinning. Self-resetting.
__device__ __forceinline__ void grid_barrier() {
    __threadfence();
    __syncthreads();
    if (threadIdx.x == 0) {
        unsigned s = g_bar_sense;
        unsigned old = atomicAdd(&g_bar_count, 1u);
        if (old == GRID - 1) {
            g_bar_count = 0;
            __threadfence();
            g_bar_sense = s ^ 1u;
        } else {
            while (g_bar_sense == s) { }
        }
        __threadfence();
    }
    __syncthreads();
}

struct Tri { float3 v0, v1, v2; };

__device__ __forceinline__ Tri load_tri(int f) {
    const float4* p = (const float4*)&g_tri[f * 12];
    float4 q0 = p[0], q1 = p[1], q2 = p[2];
    Tri t;
    t.v0 = make_float3(q0.x, q0.y, q0.z);
    t.v1 = make_float3(q0.w, q1.x, q1.y);
    t.v2 = make_float3(q1.z, q1.w, q2.x);
    return t;
}

// Cone-field penalty of src triangle A evaluated at the 3 verts of P.
// SIGMA = 0.5 -> /SIGMA == *2 (exact).
__device__ __forceinline__ float cone_pen(const Tri& A, const Tri& P) {
    float e0x = A.v1.x - A.v0.x, e0y = A.v1.y - A.v0.y, e0z = A.v1.z - A.v0.z;
    float e1x = A.v2.x - A.v0.x, e1y = A.v2.y - A.v0.y, e1z = A.v2.z - A.v0.z;

    float nx = e0y * e1z - e0z * e1y;
    float ny = e0z * e1x - e0x * e1z;
    float nz = e0x * e1y - e0y * e1x;
    float nn = sqrtf(nx * nx + ny * ny + nz * nz);
    float inv = 1.0f / (nn + EPSF);
    nx *= inv; ny *= inv; nz *= inv;

    float cx = (A.v0.x + A.v1.x + A.v2.x) * (1.0f / 3.0f);
    float cy = (A.v0.y + A.v1.y + A.v2.y) * (1.0f / 3.0f);
    float cz = (A.v0.z + A.v1.z + A.v2.z) * (1.0f / 3.0f);

    const float3* pv = &P.v0;
    float pen = 0.0f;
#pragma unroll
    for (int v = 0; v < 3; v++) {
        float ux = pv[v].x - cx;
        float uy = pv[v].y - cy;
        float uz = pv[v].z - cz;
        float h = ux * nx + uy * ny + uz * nz;
        float wx = ux - h * nx;
        float wy = uy - h * ny;
        float wz = uz - h * nz;
        float r = sqrtf(wx * wx + wy * wy + wz * wz);
        float radial = fmaxf(1.0f - r * 2.0f, 0.0f);
        float depth = fmaxf(-h, 0.0f) + fmaxf(h, 0.0f) * __expf(-h * 2.0f);
        float phi = radial * depth;
        pen += phi * phi;
    }
    return pen;
}

// ---------------------------------------------------------------------------
// ONE persistent kernel: setup | barrier | scan | barrier | eval | epilogue
// ---------------------------------------------------------------------------
__global__ void __launch_bounds__(TPB, 1)
fused_kernel(const float* __restrict__ verts,
             const int*   __restrict__ faces,
             float*       __restrict__ out) {
    __shared__ double s_bsum;
    int tid = threadIdx.x;
    if (tid == 0) s_bsum = 0.0;

    // ---------- Phase 1: setup, 4 lanes per face, all blocks active --------
    {
        int group = tid >> 2;                      // 0..255
        int l = tid & 3;
        int f = group * GRID + (int)blockIdx.x;
        int fc = (f < NUM_FACES) ? f : (NUM_FACES - 1);
        int comp = (l < 2) ? l : 2;                // lane 3 duplicates lane 2
        int idx = faces[3 * fc + comp];
        float x = verts[3 * idx + 0];
        float y = verts[3 * idx + 1];
        float z = verts[3 * idx + 2];

        if (f < NUM_FACES && l < 3) {
            g_tri[f * 12 + 3 * l + 0] = x;
            g_tri[f * 12 + 3 * l + 1] = y;
            g_tri[f * 12 + 3 * l + 2] = z;
        }

        float mnx = x, mny = y, mnz = z, mxx = x, mxy = y, mxz = z;
#pragma unroll
        for (int off = 1; off <= 2; off <<= 1) {
            mnx = fminf(mnx, __shfl_xor_sync(0xffffffffu, mnx, off));
            mny = fminf(mny, __shfl_xor_sync(0xffffffffu, mny, off));
            mnz = fminf(mnz, __shfl_xor_sync(0xffffffffu, mnz, off));
            mxx = fmaxf(mxx, __shfl_xor_sync(0xffffffffu, mxx, off));
            mxy = fmaxf(mxy, __shfl_xor_sync(0xffffffffu, mxy, off));
            mxz = fmaxf(mxz, __shfl_xor_sync(0xffffffffu, mxz, off));
        }
        int i1 = __shfl_xor_sync(0xffffffffu, idx, 1);
        int i2 = __shfl_xor_sync(0xffffffffu, idx, 2);

        if (f < NUM_FACES && l == 0) {
            g_bbmin[f] = make_float4(mnx, mny, mnz, __int_as_float(idx));
            g_bbmax[f] = make_float4(mxx, mxy, mxz, __int_as_float(i1));
            g_f2[f]    = i2;
        }
    }

    grid_barrier();   // AABBs + triangles visible device-wide

    // ---------- Phase 2: broad-phase scan, THREAD-per-row ------------------
    // 32 rows per warp; all lanes step through the SAME column j so the
    // column AABB loads are warp-uniform broadcasts. First-8-ascending per
    // row == stable top_k over the 0/1 validity matrix.
    if (tid < 96) {                      // warps 0..2: 96 rows per block
        int row = (int)blockIdx.x * 96 + tid;     // 148*96 = 14208 >= 13776
        bool haverow = row < NUM_FACES;
        float4 bmin, bmax;
        int rf0 = -1, rf1 = -1, rf2 = -1;
        if (haverow) {
            bmin = g_bbmin[row];
            bmax = g_bbmax[row];
            rf0 = __float_as_int(bmin.w);
            rf1 = __float_as_int(bmax.w);
            rf2 = g_f2[row];
        }
        int count = haverow ? 0 : MAXC;

        for (int base = 0; base < NUM_FACES; base += 4) {
            if (__all_sync(0xffffffffu, count >= MAXC)) break;
#pragma unroll
            for (int u = 0; u < 4; u++) {
                int j = base + u;                 // warp-uniform
                float4 jmin = g_bbmin[j];         // broadcast loads
                float4 jmax = g_bbmax[j];
                int    jf2  = g_f2[j];
                if (count < MAXC) {
                    bool ok = (bmin.x <= jmax.x) && (jmin.x <= bmax.x) &&
                              (bmin.y <= jmax.y) && (jmin.y <= bmax.y) &&
                              (bmin.z <= jmax.z) && (jmin.z <= bmax.z);
                    if (ok) {
                        int jf0 = __float_as_int(jmin.w);
                        int jf1 = __float_as_int(jmax.w);
                        bool share = (rf0 == jf0) | (rf0 == jf1) | (rf0 == jf2) |
                                     (rf1 == jf0) | (rf1 == jf1) | (rf1 == jf2) |
                                     (rf2 == jf0) | (rf2 == jf1) | (rf2 == jf2);
                        if (!share) {
                            g_pairs[(row << 3) + count] = j;
                            count++;
                        }
                    }
                }
            }
        }
        if (haverow) g_cnt[row] = count;
    }

    grid_barrier();   // pair lists visible device-wide

    // ---------- Phase 3: narrow phase, THREAD-per-pair (both directions) ---
    {
        int t = (int)blockIdx.x * TPB + tid;      // 151552 >= 110208 slots
        float pen = 0.0f;
        if (t < NUM_FACES * MAXC) {
            int row = t >> 3;
            int k = t & 7;
            if (k < g_cnt[row]) {
                int j = g_pairs[t];
                Tri R = load_tri(row);
                Tri J = load_tri(j);
                pen = cone_pen(R, J) + cone_pen(J, R);
            }
        }
#pragma unroll
        for (int off = 16; off > 0; off >>= 1)
            pen += __shfl_xor_sync(0xffffffffu, pen, off);
        if ((tid & 31) == 0 && pen != 0.0f) atomicAdd(&s_bsum, (double)pen);
    }
    __syncthreads();

    // ---------- Epilogue: last block writes output, resets state -----------
    if (tid == 0) {
        if (s_bsum != 0.0) atomicAdd(&g_accum, s_bsum);
        __threadfence();
        unsigned old = atomicAdd(&g_done, 1u);
        if (old == GRID - 1) {
            g_done = 0;
            unsigned long long bits =
                atomicExch((unsigned long long*)&g_accum, 0ULL);
            out[0] = (float)__longlong_as_double(bits);   // weight = 1.0
        }
    }
}

extern "C" void kernel_launch(void* const* d_in, const int* in_sizes, int n_in,
                              void* d_out, int out_size) {
    const float* verts = (const float*)d_in[0];
    const int*   faces = (const int*)d_in[1];
    float*       out   = (float*)d_out;

    fused_kernel<<<GRID, TPB>>>(verts, faces, out);
}

// round 7
// speedup vs baseline: 1.6300x; 1.6300x over previous
#include <cuda_runtime.h>

#define NUM_FACES 13776
#define MAXC 8
#define EPSF 1e-8f
#define GRID 148
#define TPB 1024
#define NCOLS0 96          // fast-path scan depth (multiple of 8)

// ---- device scratch (static; no runtime allocations) ----
__device__ float4 g_bbmin[NUM_FACES];     // (minx,miny,minz, face_id0 bits)
__device__ float4 g_bbmax[NUM_FACES];     // (maxx,maxy,maxz, face_id1 bits)
__device__ int    g_f2[NUM_FACES];        // face_id2
__device__ float  g_tri[NUM_FACES * 12];  // 9 floats per face, padded to 48B
__device__ int    g_cnt[NUM_FACES];       // collisions per row (<= 8)
__device__ int    g_pairs[NUM_FACES * MAXC];
__device__ int    g_strag[NUM_FACES];     // straggler worklist
__device__ int    g_ns;                   // worklist size
__device__ int    g_widx;                 // worklist grab cursor
__device__ double g_accum;
__device__ unsigned g_bar_count;
__device__ volatile unsigned g_bar_sense;
__device__ unsigned g_done;

// Sense-reversing grid barrier. Safe: 148 blocks x 1024 thr at 1 block/SM ->
// wave-1 placement keeps every block resident while spinning. Self-resetting.
__device__ __forceinline__ void grid_barrier() {
    __threadfence();
    __syncthreads();
    if (threadIdx.x == 0) {
        unsigned s = g_bar_sense;
        unsigned old = atomicAdd(&g_bar_count, 1u);
        if (old == GRID - 1) {
            g_bar_count = 0;
            __threadfence();
            g_bar_sense = s ^ 1u;
        } else {
            while (g_bar_sense == s) { __nanosleep(64); }
        }
        __threadfence();
    }
    __syncthreads();
}

struct Tri { float3 v0, v1, v2; };

__device__ __forceinline__ Tri load_tri(int f) {
    const float4* p = (const float4*)&g_tri[f * 12];
    float4 q0 = p[0], q1 = p[1], q2 = p[2];
    Tri t;
    t.v0 = make_float3(q0.x, q0.y, q0.z);
    t.v1 = make_float3(q0.w, q1.x, q1.y);
    t.v2 = make_float3(q1.z, q1.w, q2.x);
    return t;
}

// Cone-field penalty of src triangle A at the 3 verts of P. SIGMA=0.5 -> *2.
__device__ __forceinline__ float cone_pen(const Tri& A, const Tri& P) {
    float e0x = A.v1.x - A.v0.x, e0y = A.v1.y - A.v0.y, e0z = A.v1.z - A.v0.z;
    float e1x = A.v2.x - A.v0.x, e1y = A.v2.y - A.v0.y, e1z = A.v2.z - A.v0.z;

    float nx = e0y * e1z - e0z * e1y;
    float ny = e0z * e1x - e0x * e1z;
    float nz = e0x * e1y - e0y * e1x;
    float nn = sqrtf(nx * nx + ny * ny + nz * nz);
    float inv = 1.0f / (nn + EPSF);
    nx *= inv; ny *= inv; nz *= inv;

    float cx = (A.v0.x + A.v1.x + A.v2.x) * (1.0f / 3.0f);
    float cy = (A.v0.y + A.v1.y + A.v2.y) * (1.0f / 3.0f);
    float cz = (A.v0.z + A.v1.z + A.v2.z) * (1.0f / 3.0f);

    const float3* pv = &P.v0;
    float pen = 0.0f;
#pragma unroll
    for (int v = 0; v < 3; v++) {
        float ux = pv[v].x - cx;
        float uy = pv[v].y - cy;
        float uz = pv[v].z - cz;
        float h = ux * nx + uy * ny + uz * nz;
        float wx = ux - h * nx;
        float wy = uy - h * ny;
        float wz = uz - h * nz;
        float r = sqrtf(wx * wx + wy * wy + wz * wz);
        float radial = fmaxf(1.0f - r * 2.0f, 0.0f);
        float depth = fmaxf(-h, 0.0f) + fmaxf(h, 0.0f) * __expf(-h * 2.0f);
        float phi = radial * depth;
        pen += phi * phi;
    }
    return pen;
}

__device__ __forceinline__ bool pair_ok(const float4& bmin, const float4& bmax,
                                        int rf0, int rf1, int rf2,
                                        const float4& jmin, const float4& jmax,
                                        int jf2) {
    bool ok = (bmin.x <= jmax.x) && (jmin.x <= bmax.x) &&
              (bmin.y <= jmax.y) && (jmin.y <= bmax.y) &&
              (bmin.z <= jmax.z) && (jmin.z <= bmax.z);
    if (ok) {
        int jf0 = __float_as_int(jmin.w);
        int jf1 = __float_as_int(jmax.w);
        bool share = (rf0 == jf0) | (rf0 == jf1) | (rf0 == jf2) |
                     (rf1 == jf0) | (rf1 == jf1) | (rf1 == jf2) |
                     (rf2 == jf0) | (rf2 == jf1) | (rf2 == jf2);
        ok = !share;
    }
    return ok;
}

// ---------------------------------------------------------------------------
// ONE persistent kernel:
//   setup | bar | fast scan (96 cols) | bar | straggler scan (block/row) |
//   bar | narrow phase | epilogue
// ---------------------------------------------------------------------------
__global__ void __launch_bounds__(TPB, 1)
fused_kernel(const float* __restrict__ verts,
             const int*   __restrict__ faces,
             float*       __restrict__ out) {
    __shared__ double   s_bsum;
    __shared__ unsigned s_mask[32];
    __shared__ int      s_pref[32];
    __shared__ int      s_tot, s_found, s_row;

    int tid = threadIdx.x;
    if (tid == 0) s_bsum = 0.0;
    if (blockIdx.x == 0 && tid == 0) { g_ns = 0; g_widx = 0; }

    // ---------- Phase 1: setup, 4 lanes per face ---------------------------
    {
        int group = tid >> 2;
        int l = tid & 3;
        int f = group * GRID + (int)blockIdx.x;
        int fc = (f < NUM_FACES) ? f : (NUM_FACES - 1);
        int comp = (l < 2) ? l : 2;
        int idx = faces[3 * fc + comp];
        float x = verts[3 * idx + 0];
        float y = verts[3 * idx + 1];
        float z = verts[3 * idx + 2];

        if (f < NUM_FACES && l < 3) {
            g_tri[f * 12 + 3 * l + 0] = x;
            g_tri[f * 12 + 3 * l + 1] = y;
            g_tri[f * 12 + 3 * l + 2] = z;
        }

        float mnx = x, mny = y, mnz = z, mxx = x, mxy = y, mxz = z;
#pragma unroll
        for (int off = 1; off <= 2; off <<= 1) {
            mnx = fminf(mnx, __shfl_xor_sync(0xffffffffu, mnx, off));
            mny = fminf(mny, __shfl_xor_sync(0xffffffffu, mny, off));
            mnz = fminf(mnz, __shfl_xor_sync(0xffffffffu, mnz, off));
            mxx = fmaxf(mxx, __shfl_xor_sync(0xffffffffu, mxx, off));
            mxy = fmaxf(mxy, __shfl_xor_sync(0xffffffffu, mxy, off));
            mxz = fmaxf(mxz, __shfl_xor_sync(0xffffffffu, mxz, off));
        }
        int i1 = __shfl_xor_sync(0xffffffffu, idx, 1);
        int i2 = __shfl_xor_sync(0xffffffffu, idx, 2);

        if (f < NUM_FACES && l == 0) {
            g_bbmin[f] = make_float4(mnx, mny, mnz, __int_as_float(idx));
            g_bbmax[f] = make_float4(mxx, mxy, mxz, __int_as_float(i1));
            g_f2[f]    = i2;
        }
    }

    grid_barrier();   // AABBs + triangles + reset counters visible

    // ---------- Phase 2a: fast scan, thread-per-row over first 96 columns --
    if (tid < 96) {
        int row = (int)blockIdx.x * 96 + tid;     // 148*96 = 14208 >= 13776
        bool haverow = row < NUM_FACES;
        float4 bmin, bmax;
        int rf0 = -1, rf1 = -1, rf2 = -1;
        if (haverow) {
            bmin = g_bbmin[row];
            bmax = g_bbmax[row];
            rf0 = __float_as_int(bmin.w);
            rf1 = __float_as_int(bmax.w);
            rf2 = g_f2[row];
        }
        int count = haverow ? 0 : MAXC;

        for (int base = 0; base < NCOLS0; base += 8) {
            if (__all_sync(0xffffffffu, count >= MAXC)) break;
#pragma unroll
            for (int u = 0; u < 8; u++) {
                int j = base + u;                 // warp-uniform column
                float4 jmin = g_bbmin[j];         // broadcast loads
                float4 jmax = g_bbmax[j];
                int    jf2  = g_f2[j];
                if (count < MAXC &&
                    pair_ok(bmin, bmax, rf0, rf1, rf2, jmin, jmax, jf2)) {
                    g_pairs[(row << 3) + count] = j;
                    count++;
                }
            }
        }
        if (haverow) {
            g_cnt[row] = count;
            if (count < MAXC) {                   // straggler -> worklist
                int w = atomicAdd(&g_ns, 1);
                g_strag[w] = row;
            }
        }
    }

    grid_barrier();   // pair lists + worklist visible

    // ---------- Phase 2b: straggler scan, BLOCK-per-row, 1024 cols/iter ----
    {
        int ns = g_ns;
        for (;;) {
            if (tid == 0) s_row = atomicAdd(&g_widx, 1);
            __syncthreads();
            int w = s_row;
            if (w >= ns) break;
            int row = g_strag[w];

            float4 bmin = g_bbmin[row];
            float4 bmax = g_bbmax[row];
            int rf0 = __float_as_int(bmin.w);
            int rf1 = __float_as_int(bmax.w);
            int rf2 = g_f2[row];
            if (tid == 0) s_found = g_cnt[row];
            __syncthreads();

            for (int base = NCOLS0; base < NUM_FACES; base += TPB) {
                int j = base + tid;
                bool ok = false;
                if (j < NUM_FACES) {
                    float4 jmin = g_bbmin[j];
                    float4 jmax = g_bbmax[j];
                    ok = pair_ok(bmin, bmax, rf0, rf1, rf2, jmin, jmax, g_f2[j]);
                }
                unsigned m = __ballot_sync(0xffffffffu, ok);
                if ((tid & 31) == 0) s_mask[tid >> 5] = m;
                __syncthreads();
                if (tid < 32) {                   // warp 0: exclusive prefix
                    int c = __popc(s_mask[tid]);
                    int incl = c;
#pragma unroll
                    for (int off = 1; off < 32; off <<= 1) {
                        int v = __shfl_up_sync(0xffffffffu, incl, off);
                        if (tid >= off) incl += v;
                    }
                    s_pref[tid] = incl - c;
                    if (tid == 31) s_tot = incl;
                }
                __syncthreads();
                int before = s_found;
                if (ok) {
                    int rank = before + s_pref[tid >> 5] +
                               __popc(s_mask[tid >> 5] & ((1u << (tid & 31)) - 1u));
                    if (rank < MAXC) g_pairs[(row << 3) + rank] = j;
                }
                __syncthreads();
                if (tid == 0) s_found = before + s_tot;
                __syncthreads();
                if (s_found >= MAXC) break;
            }
            if (tid == 0) g_cnt[row] = min(s_found, MAXC);
            __syncthreads();
        }
    }

    grid_barrier();   // all pair lists final

    // ---------- Phase 3: narrow phase, thread-per-pair (both directions) ---
    {
        int t = (int)blockIdx.x * TPB + tid;      // 151552 >= 110208 slots
        float pen = 0.0f;
        if (t < NUM_FACES * MAXC) {
            int row = t >> 3;
            int k = t & 7;
            if (k < g_cnt[row]) {
                int j = g_pairs[t];
                Tri R = load_tri(row);
                Tri J = load_tri(j);
                pen = cone_pen(R, J) + cone_pen(J, R);
            }
        }
#pragma unroll
        for (int off = 16; off > 0; off >>= 1)
            pen += __shfl_xor_sync(0xffffffffu, pen, off);
        if ((tid & 31) == 0 && pen != 0.0f) atomicAdd(&s_bsum, (double)pen);
    }
    __syncthreads();

    // ---------- Epilogue: last block writes output, resets state -----------
    if (tid == 0) {
        if (s_bsum != 0.0) atomicAdd(&g_accum, s_bsum);
        __threadfence();
        unsigned old = atomicAdd(&g_done, 1u);
        if (old == GRID - 1) {
            g_done = 0;
            unsigned long long bits =
                atomicExch((unsigned long long*)&g_accum, 0ULL);
            out[0] = (float)__longlong_as_double(bits);   // weight = 1.0
        }
    }
}

extern "C" void kernel_launch(void* const* d_in, const int* in_sizes, int n_in,
                              void* d_out, int out_size) {
    const float* verts = (const float*)d_in[0];
    const int*   faces = (const int*)d_in[1];
    float*       out   = (float*)d_out;

    fused_kernel<<<GRID, TPB>>>(verts, faces, out);
}

// round 8
// speedup vs baseline: 2.3923x; 1.4677x over previous
#include <cuda_runtime.h>

#define NUM_FACES 13776
#define MAXC 8
#define EPSF 1e-8f
#define GRID 148
#define TPB 1024
#define NWARPS (GRID * (TPB / 32))   // 4736
#define NCOLS0 128                   // fast-path scan depth (4 chunks of 32)

// ---- device scratch (static; no runtime allocations) ----
__device__ float4 g_bbmin[NUM_FACES];     // (minx,miny,minz, face_id0 bits)
__device__ float4 g_bbmax[NUM_FACES];     // (maxx,maxy,maxz, face_id1 bits)
__device__ int    g_f2[NUM_FACES];        // face_id2
__device__ float  g_tri[NUM_FACES * 12];  // 9 floats per face, padded to 48B
__device__ int    g_cnt[NUM_FACES];       // collisions per row (<= 8)
__device__ int    g_pairs[NUM_FACES * MAXC];
__device__ int    g_strag[NUM_FACES];     // straggler worklist
__device__ int    g_ns;                   // worklist size
__device__ int    g_widx;                 // worklist grab cursor
__device__ double g_accum;
__device__ unsigned g_bar_count;
__device__ volatile unsigned g_bar_sense;
__device__ unsigned g_done;

// Sense-reversing grid barrier. Safe: 148 blocks x 1024 thr at 1 block/SM ->
// wave-1 placement keeps every block resident while spinning. Self-resetting.
__device__ __forceinline__ void grid_barrier() {
    __threadfence();
    __syncthreads();
    if (threadIdx.x == 0) {
        unsigned s = g_bar_sense;
        unsigned old = atomicAdd(&g_bar_count, 1u);
        if (old == GRID - 1) {
            g_bar_count = 0;
            __threadfence();
            g_bar_sense = s ^ 1u;
        } else {
            while (g_bar_sense == s) { __nanosleep(64); }
        }
        __threadfence();
    }
    __syncthreads();
}

struct Tri { float3 v0, v1, v2; };

__device__ __forceinline__ Tri load_tri(int f) {
    const float4* p = (const float4*)&g_tri[f * 12];
    float4 q0 = p[0], q1 = p[1], q2 = p[2];
    Tri t;
    t.v0 = make_float3(q0.x, q0.y, q0.z);
    t.v1 = make_float3(q0.w, q1.x, q1.y);
    t.v2 = make_float3(q1.z, q1.w, q2.x);
    return t;
}

// Cone-field penalty of src triangle A at the 3 verts of P. SIGMA=0.5 -> *2.
__device__ __forceinline__ float cone_pen(const Tri& A, const Tri& P) {
    float e0x = A.v1.x - A.v0.x, e0y = A.v1.y - A.v0.y, e0z = A.v1.z - A.v0.z;
    float e1x = A.v2.x - A.v0.x, e1y = A.v2.y - A.v0.y, e1z = A.v2.z - A.v0.z;

    float nx = e0y * e1z - e0z * e1y;
    float ny = e0z * e1x - e0x * e1z;
    float nz = e0x * e1y - e0y * e1x;
    float nn = sqrtf(nx * nx + ny * ny + nz * nz);
    float inv = 1.0f / (nn + EPSF);
    nx *= inv; ny *= inv; nz *= inv;

    float cx = (A.v0.x + A.v1.x + A.v2.x) * (1.0f / 3.0f);
    float cy = (A.v0.y + A.v1.y + A.v2.y) * (1.0f / 3.0f);
    float cz = (A.v0.z + A.v1.z + A.v2.z) * (1.0f / 3.0f);

    const float3* pv = &P.v0;
    float pen = 0.0f;
#pragma unroll
    for (int v = 0; v < 3; v++) {
        float ux = pv[v].x - cx;
        float uy = pv[v].y - cy;
        float uz = pv[v].z - cz;
        float h = ux * nx + uy * ny + uz * nz;
        float wx = ux - h * nx;
        float wy = uy - h * ny;
        float wz = uz - h * nz;
        float r = sqrtf(wx * wx + wy * wy + wz * wz);
        float radial = fmaxf(1.0f - r * 2.0f, 0.0f);
        float depth = fmaxf(-h, 0.0f) + fmaxf(h, 0.0f) * __expf(-h * 2.0f);
        float phi = radial * depth;
        pen += phi * phi;
    }
    return pen;
}

__device__ __forceinline__ bool pair_ok(const float4& bmin, const float4& bmax,
                                        int rf0, int rf1, int rf2,
                                        const float4& jmin, const float4& jmax,
                                        int jf2) {
    bool ok = (bmin.x <= jmax.x) && (jmin.x <= bmax.x) &&
              (bmin.y <= jmax.y) && (jmin.y <= bmax.y) &&
              (bmin.z <= jmax.z) && (jmin.z <= bmax.z);
    if (ok) {
        int jf0 = __float_as_int(jmin.w);
        int jf1 = __float_as_int(jmax.w);
        bool share = (rf0 == jf0) | (rf0 == jf1) | (rf0 == jf2) |
                     (rf1 == jf0) | (rf1 == jf1) | (rf1 == jf2) |
                     (rf2 == jf0) | (rf2 == jf1) | (rf2 == jf2);
        ok = !share;
    }
    return ok;
}

// ---------------------------------------------------------------------------
// ONE persistent kernel:
//   setup | bar | WARP-per-row scan (128 cols) | bar |
//   BLOCK-per-straggler-row scan | bar | narrow phase | epilogue
// All phases keep all 32 warps of every block active.
// ---------------------------------------------------------------------------
__global__ void __launch_bounds__(TPB, 1)
fused_kernel(const float* __restrict__ verts,
             const int*   __restrict__ faces,
             float*       __restrict__ out) {
    __shared__ double   s_bsum;
    __shared__ unsigned s_mask[32];
    __shared__ int      s_pref[32];
    __shared__ int      s_tot, s_found, s_row;

    int tid = threadIdx.x;
    int lane = tid & 31;
    int wwid = tid >> 5;
    if (tid == 0) s_bsum = 0.0;
    if (blockIdx.x == 0 && tid == 0) { g_ns = 0; g_widx = 0; }

    // ---------- Phase 1: setup, 4 lanes per face ---------------------------
    {
        int group = tid >> 2;
        int l = tid & 3;
        int f = group * GRID + (int)blockIdx.x;
        int fc = (f < NUM_FACES) ? f : (NUM_FACES - 1);
        int comp = (l < 2) ? l : 2;
        int idx = faces[3 * fc + comp];
        float x = verts[3 * idx + 0];
        float y = verts[3 * idx + 1];
        float z = verts[3 * idx + 2];

        if (f < NUM_FACES && l < 3) {
            g_tri[f * 12 + 3 * l + 0] = x;
            g_tri[f * 12 + 3 * l + 1] = y;
            g_tri[f * 12 + 3 * l + 2] = z;
        }

        float mnx = x, mny = y, mnz = z, mxx = x, mxy = y, mxz = z;
#pragma unroll
        for (int off = 1; off <= 2; off <<= 1) {
            mnx = fminf(mnx, __shfl_xor_sync(0xffffffffu, mnx, off));
            mny = fminf(mny, __shfl_xor_sync(0xffffffffu, mny, off));
            mnz = fminf(mnz, __shfl_xor_sync(0xffffffffu, mnz, off));
            mxx = fmaxf(mxx, __shfl_xor_sync(0xffffffffu, mxx, off));
            mxy = fmaxf(mxy, __shfl_xor_sync(0xffffffffu, mxy, off));
            mxz = fmaxf(mxz, __shfl_xor_sync(0xffffffffu, mxz, off));
        }
        int i1 = __shfl_xor_sync(0xffffffffu, idx, 1);
        int i2 = __shfl_xor_sync(0xffffffffu, idx, 2);

        if (f < NUM_FACES && l == 0) {
            g_bbmin[f] = make_float4(mnx, mny, mnz, __int_as_float(idx));
            g_bbmax[f] = make_float4(mxx, mxy, mxz, __int_as_float(i1));
            g_f2[f]    = i2;
        }
    }

    grid_barrier();   // AABBs + triangles + reset counters visible

    // ---------- Phase 2a: WARP-per-row scan over first 128 columns ---------
    // All 32 warps/block active. Per chunk: 32 lanes test 32 columns,
    // ballot + prefix-popc gives ascending ranks (== stable top_k order).
    {
        int gwarp = (int)blockIdx.x * 32 + wwid;
        for (int row = gwarp; row < NUM_FACES; row += NWARPS) {
            float4 bmin = g_bbmin[row];
            float4 bmax = g_bbmax[row];
            int rf0 = __float_as_int(bmin.w);
            int rf1 = __float_as_int(bmax.w);
            int rf2 = g_f2[row];

            int found = 0;
#pragma unroll
            for (int c = 0; c < NCOLS0 / 32; c++) {
                if (found >= MAXC) break;
                int j = (c << 5) + lane;
                float4 jmin = g_bbmin[j];
                float4 jmax = g_bbmax[j];
                bool ok = pair_ok(bmin, bmax, rf0, rf1, rf2, jmin, jmax, g_f2[j]);
                unsigned m = __ballot_sync(0xffffffffu, ok);
                int rank = found + __popc(m & ((1u << lane) - 1u));
                if (ok && rank < MAXC) g_pairs[(row << 3) + rank] = j;
                found += __popc(m);
            }
            int cnt = min(found, MAXC);
            if (lane == 0) {
                g_cnt[row] = cnt;
                if (cnt < MAXC) {                 // straggler -> worklist
                    int w = atomicAdd(&g_ns, 1);
                    g_strag[w] = row;
                }
            }
        }
    }

    grid_barrier();   // pair lists + worklist visible

    // ---------- Phase 2b: straggler scan, BLOCK-per-row, 1024 cols/iter ----
    {
        int ns = g_ns;
        for (;;) {
            if (tid == 0) s_row = atomicAdd(&g_widx, 1);
            __syncthreads();
            int w = s_row;
            if (w >= ns) break;
            int row = g_strag[w];

            float4 bmin = g_bbmin[row];
            float4 bmax = g_bbmax[row];
            int rf0 = __float_as_int(bmin.w);
            int rf1 = __float_as_int(bmax.w);
            int rf2 = g_f2[row];
            if (tid == 0) s_found = g_cnt[row];
            __syncthreads();

            for (int base = NCOLS0; base < NUM_FACES; base += TPB) {
                int j = base + tid;
                bool ok = false;
                if (j < NUM_FACES) {
                    float4 jmin = g_bbmin[j];
                    float4 jmax = g_bbmax[j];
                    ok = pair_ok(bmin, bmax, rf0, rf1, rf2, jmin, jmax, g_f2[j]);
                }
                unsigned m = __ballot_sync(0xffffffffu, ok);
                if (lane == 0) s_mask[wwid] = m;
                __syncthreads();
                if (tid < 32) {                   // warp 0: exclusive prefix
                    int c = __popc(s_mask[tid]);
                    int incl = c;
#pragma unroll
                    for (int off = 1; off < 32; off <<= 1) {
                        int v = __shfl_up_sync(0xffffffffu, incl, off);
                        if (tid >= off) incl += v;
                    }
                    s_pref[tid] = incl - c;
                    if (tid == 31) s_tot = incl;
                }
                __syncthreads();
                int before = s_found;
                if (ok) {
                    int rank = before + s_pref[wwid] +
                               __popc(s_mask[wwid] & ((1u << lane) - 1u));
                    if (rank < MAXC) g_pairs[(row << 3) + rank] = j;
                }
                __syncthreads();
                if (tid == 0) s_found = before + s_tot;
                __syncthreads();
                if (s_found >= MAXC) break;
            }
            if (tid == 0) g_cnt[row] = min(s_found, MAXC);
            __syncthreads();
        }
    }

    grid_barrier();   // all pair lists final

    // ---------- Phase 3: narrow phase, thread-per-pair (both directions) ---
    {
        int t = (int)blockIdx.x * TPB + tid;      // 151552 >= 110208 slots
        float pen = 0.0f;
        if (t < NUM_FACES * MAXC) {
            int row = t >> 3;
            int k = t & 7;
            if (k < g_cnt[row]) {
                int j = g_pairs[t];
                Tri R = load_tri(row);
                Tri J = load_tri(j);
                pen = cone_pen(R, J) + cone_pen(J, R);
            }
        }
#pragma unroll
        for (int off = 16; off > 0; off >>= 1)
            pen += __shfl_xor_sync(0xffffffffu, pen, off);
        if (lane == 0 && pen != 0.0f) atomicAdd(&s_bsum, (double)pen);
    }
    __syncthreads();

    // ---------- Epilogue: last block writes output, resets state -----------
    if (tid == 0) {
        if (s_bsum != 0.0) atomicAdd(&g_accum, s_bsum);
        __threadfence();
        unsigned old = atomicAdd(&g_done, 1u);
        if (old == GRID - 1) {
            g_done = 0;
            unsigned long long bits =
                atomicExch((unsigned long long*)&g_accum, 0ULL);
            out[0] = (float)__longlong_as_double(bits);   // weight = 1.0
        }
    }
}

extern "C" void kernel_launch(void* const* d_in, const int* in_sizes, int n_in,
                              void* d_out, int out_size) {
    const float* verts = (const float*)d_in[0];
    const int*   faces = (const int*)d_in[1];
    float*       out   = (float*)d_out;

    fused_kernel<<<GRID, TPB>>>(verts, faces, out);
}